// round 5
// baseline (speedup 1.0000x reference)
#include <cuda_runtime.h>
#include <math.h>

// Problem constants
#define BB 64
#define TT 256
#define DD 512
#define HH 1024         // H1 == H2
#define G4 4096         // 4*H
#define OO 512
#define MTOT (BB*TT)    // 16384

// ---------------------------------------------------------------------------
// Static device scratch (no allocations allowed in kernel_launch)
// ---------------------------------------------------------------------------
__device__ float g_xz[(size_t)MTOT * G4];     // 256 MB: xz for current layer (reused)
__device__ float g_seq1[(size_t)MTOT * HH];   // 64 MB: layer-1 hidden sequence [t][b][u]
__device__ float g_hbuf[2][BB * HH];          // ping-pong h
__device__ float g_cbuf[BB * HH];             // c state (in-place, per-unit ownership)
__device__ float g_Wp[(size_t)HH * G4];       // permuted W (gate-interleaved)
__device__ float g_Up[(size_t)HH * G4];       // permuted U (gate-interleaved)
__device__ float g_bp[G4];                    // permuted bias

// ---------------------------------------------------------------------------
// Permute weights into gate-interleaved layout: dst[k][u*4+g] = src[k][g*H+u]
// dst_sel: 0 = g_Wp, 1 = g_Up, 2 = g_bp
// ---------------------------------------------------------------------------
__global__ void permute_gates(const float* __restrict__ src, int K, int dst_sel)
{
    float* dst = (dst_sel == 0) ? g_Wp : (dst_sel == 1) ? g_Up : g_bp;
    int idx = blockIdx.x * blockDim.x + threadIdx.x;
    int total = K * G4;
    if (idx >= total) return;
    int k   = idx >> 12;       // / 4096
    int col = idx & 4095;
    int u   = col >> 2;
    int g   = col & 3;
    dst[idx] = src[(size_t)k * G4 + g * HH + u];
}

// ---------------------------------------------------------------------------
// Zero h/c state before each layer
// ---------------------------------------------------------------------------
__global__ void zero_hc()
{
    int idx = blockIdx.x * blockDim.x + threadIdx.x;
    if (idx < BB * HH) {
        g_hbuf[0][idx] = 0.f;
        g_hbuf[1][idx] = 0.f;
        g_cbuf[idx]    = 0.f;
    }
}

// ---------------------------------------------------------------------------
// Big GEMM: out[m][n] = sum_k A[m][k] * Wp[k][n] + bp[n]
//   m = t*B + b (output is [T][B][4096] gate-interleaved)
//   MODE 0: A = x with layout [b][t][d] (K = 512), A passed as param
//   MODE 1: A = g_seq1, plain row-major [m][k] (K = 1024)
// 128x128x16 tiles, 256 threads, 8x8 microtile (split 4+4 to reduce LDS conflicts)
// ---------------------------------------------------------------------------
template<int MODE>
__global__ __launch_bounds__(256) void gemm_big(const float* __restrict__ Ain, int K)
{
    __shared__ float As[16][136];
    __shared__ float Bs[16][136];

    const int tid  = threadIdx.x;
    const int tx   = tid & 15;
    const int ty   = tid >> 4;
    const int row0 = blockIdx.y * 128;
    const int n0   = blockIdx.x * 128;

    const float* A = (MODE == 0) ? Ain : (const float*)g_seq1;

    float bias[8];
#pragma unroll
    for (int j = 0; j < 4; j++) {
        bias[j]     = g_bp[n0 + tx * 4 + j];
        bias[4 + j] = g_bp[n0 + 64 + tx * 4 + j];
    }
    float acc[8][8];
#pragma unroll
    for (int r = 0; r < 8; r++)
#pragma unroll
        for (int c = 0; c < 8; c++) acc[r][c] = bias[c];

    for (int k0 = 0; k0 < K; k0 += 16) {
        // A tile (128 x 16), stored transposed As[k][m]
#pragma unroll
        for (int l = 0; l < 2; l++) {
            int lin = tid + l * 256;
            int m = lin >> 2, q = lin & 3;
            int mg = row0 + m;
            const float* ap;
            if (MODE == 0) {
                int t_ = mg >> 6, b_ = mg & 63;
                ap = A + ((size_t)(b_ * TT + t_)) * DD;
            } else {
                ap = A + (size_t)mg * K;
            }
            float4 v = *(const float4*)(ap + k0 + q * 4);
            As[q * 4 + 0][m] = v.x;
            As[q * 4 + 1][m] = v.y;
            As[q * 4 + 2][m] = v.z;
            As[q * 4 + 3][m] = v.w;
        }
        // B tile (16 x 128)
#pragma unroll
        for (int l = 0; l < 2; l++) {
            int lin = tid + l * 256;
            int kk = lin >> 5, q = lin & 31;
            float4 v = *(const float4*)(g_Wp + (size_t)(k0 + kk) * G4 + n0 + q * 4);
            *(float4*)&Bs[kk][q * 4] = v;
        }
        __syncthreads();
#pragma unroll
        for (int k = 0; k < 16; k++) {
            float a[8], b[8];
            *(float4*)&a[0] = *(float4*)&As[k][ty * 4];
            *(float4*)&a[4] = *(float4*)&As[k][64 + ty * 4];
            *(float4*)&b[0] = *(float4*)&Bs[k][tx * 4];
            *(float4*)&b[4] = *(float4*)&Bs[k][64 + tx * 4];
#pragma unroll
            for (int r = 0; r < 8; r++)
#pragma unroll
                for (int c = 0; c < 8; c++)
                    acc[r][c] += a[r] * b[c];
        }
        __syncthreads();
    }

#pragma unroll
    for (int r = 0; r < 8; r++) {
        int m = row0 + ((r < 4) ? (ty * 4 + r) : (64 + ty * 4 + (r - 4)));
        float* op = g_xz + (size_t)m * G4 + n0;
        float4 v0 = make_float4(acc[r][0], acc[r][1], acc[r][2], acc[r][3]);
        float4 v1 = make_float4(acc[r][4], acc[r][5], acc[r][6], acc[r][7]);
        *(float4*)(op + tx * 4)      = v0;
        *(float4*)(op + 64 + tx * 4) = v1;
    }
}

// ---------------------------------------------------------------------------
// One recurrence step: z = xz[t] + h_prev @ Up ; gates ; update c, h
// Grid: 128 CTAs (8 units = 32 gate-interleaved columns each), 256 threads.
// Each thread: column tx (0..31), rows wy*8 .. wy*8+7 of batch (64 rows).
// layer==0 also writes h_new into g_seq1[t].
// ---------------------------------------------------------------------------
__global__ __launch_bounds__(256) void lstm_step(int t, int layer)
{
    __shared__ float sh_h[64][32];
    __shared__ float sh_U[32][32];
    __shared__ float sh_z[64][33];

    const int tid = threadIdx.x;
    const int tx  = tid & 31;
    const int wy  = tid >> 5;            // 0..7
    const int c0  = blockIdx.x * 32;     // column base in [0, 4096)

    const float* xz_t   = g_xz + (size_t)t * BB * G4;
    const float* h_prev = g_hbuf[t & 1];
    float*       h_new  = g_hbuf[(t + 1) & 1];

    float acc[8];
#pragma unroll
    for (int r = 0; r < 8; r++)
        acc[r] = xz_t[(size_t)(wy * 8 + r) * G4 + c0 + tx];

    for (int k0 = 0; k0 < HH; k0 += 32) {
        // h tile 64x32 (natural layout, fully coalesced float4)
#pragma unroll
        for (int l = 0; l < 2; l++) {
            int lin = tid + l * 256;
            int m = lin >> 3, q = lin & 7;
            *(float4*)&sh_h[m][q * 4] =
                *(const float4*)(h_prev + (size_t)m * HH + k0 + q * 4);
        }
        // U tile 32x32
        {
            int kk = tid >> 3, q = tid & 7;
            *(float4*)&sh_U[kk][q * 4] =
                *(const float4*)(g_Up + (size_t)(k0 + kk) * G4 + c0 + q * 4);
        }
        __syncthreads();
#pragma unroll
        for (int q = 0; q < 8; q++) {
            float u0 = sh_U[q * 4 + 0][tx];
            float u1 = sh_U[q * 4 + 1][tx];
            float u2 = sh_U[q * 4 + 2][tx];
            float u3 = sh_U[q * 4 + 3][tx];
#pragma unroll
            for (int r = 0; r < 8; r++) {
                float4 hv = *(float4*)&sh_h[wy * 8 + r][q * 4];
                acc[r] += hv.x * u0 + hv.y * u1 + hv.z * u2 + hv.w * u3;
            }
        }
        __syncthreads();
    }

    // stage z tile and apply gates
#pragma unroll
    for (int r = 0; r < 8; r++) sh_z[wy * 8 + r][tx] = acc[r];
    __syncthreads();

#pragma unroll
    for (int l = 0; l < 2; l++) {
        int item = tid + l * 256;   // 512 (m, unit) items
        int m = item >> 3, u = item & 7;
        float zi = sh_z[m][u * 4 + 0];
        float zf = sh_z[m][u * 4 + 1];
        float zg = sh_z[m][u * 4 + 2];
        float zo = sh_z[m][u * 4 + 3];
        int uu  = (c0 >> 2) + u;            // global unit index
        int idx = m * HH + uu;
        float cold = g_cbuf[idx];
        float si = 1.f / (1.f + __expf(-zi));
        float sf = 1.f / (1.f + __expf(-zf));
        float so = 1.f / (1.f + __expf(-zo));
        float tg = tanhf(zg);
        float cn = sf * cold + si * tg;
        float hn = so * tanhf(cn);
        g_cbuf[idx] = cn;
        h_new[idx]  = hn;
        if (layer == 0)
            g_seq1[(size_t)t * BB * HH + idx] = hn;
    }
}

// ---------------------------------------------------------------------------
// Final dense: out[b][o] = h_last[b] . Wd[:,o] + bd[o]
// ---------------------------------------------------------------------------
__global__ void dense_out(const float* __restrict__ Wd, const float* __restrict__ bd,
                          float* __restrict__ out)
{
    int b = blockIdx.x;        // 64
    int o = threadIdx.x;       // 512
    const float* hp = g_hbuf[0] + (size_t)b * HH;   // T even -> final h lives in buf 0
    float acc = bd[o];
#pragma unroll 8
    for (int k = 0; k < HH; k++)
        acc += hp[k] * Wd[(size_t)k * OO + o];
    out[(size_t)b * OO + o] = acc;
}

// ---------------------------------------------------------------------------
// Launch sequence (graph-capturable: kernel launches only)
// ---------------------------------------------------------------------------
extern "C" void kernel_launch(void* const* d_in, const int* in_sizes, int n_in,
                              void* d_out, int out_size)
{
    const float* x  = (const float*)d_in[0];
    const float* W1 = (const float*)d_in[1];
    const float* U1 = (const float*)d_in[2];
    const float* b1 = (const float*)d_in[3];
    const float* W2 = (const float*)d_in[4];
    const float* U2 = (const float*)d_in[5];
    const float* b2 = (const float*)d_in[6];
    const float* Wd = (const float*)d_in[7];
    const float* bd = (const float*)d_in[8];
    float* out = (float*)d_out;

    dim3 gemm_grid(G4 / 128, MTOT / 128);

    // ---- Layer 1 ----
    permute_gates<<<(DD * G4 + 255) / 256, 256>>>(W1, DD, 0);
    permute_gates<<<(HH * G4 + 255) / 256, 256>>>(U1, HH, 1);
    permute_gates<<<(G4 + 255) / 256, 256>>>(b1, 1, 2);
    zero_hc<<<(BB * HH + 255) / 256, 256>>>();
    gemm_big<0><<<gemm_grid, 256>>>(x, DD);
    for (int t = 0; t < TT; t++)
        lstm_step<<<128, 256>>>(t, 0);

    // ---- Layer 2 ----
    permute_gates<<<(HH * G4 + 255) / 256, 256>>>(W2, HH, 0);
    permute_gates<<<(HH * G4 + 255) / 256, 256>>>(U2, HH, 1);
    permute_gates<<<(G4 + 255) / 256, 256>>>(b2, 1, 2);
    zero_hc<<<(BB * HH + 255) / 256, 256>>>();
    gemm_big<1><<<gemm_grid, 256>>>(nullptr, HH);
    for (int t = 0; t < TT; t++)
        lstm_step<<<128, 256>>>(t, 1);

    // ---- Dense head ----
    dense_out<<<BB, OO>>>(Wd, bd, out);
}